// round 11
// baseline (speedup 1.0000x reference)
#include <cuda_runtime.h>
#include <cuda_bf16.h>
#include <cstdint>

// LGMLoss on GB300 — Round 11: single plain kernel, NO device barrier,
// NO B' GMEM round-trip. Each CTA converts its own means/vars slice to
// bf16 pairs in smem. BM=32 x BN=128, grid 128, ticket-combined halves.

#define B_BATCH 2048
#define C_CLS   256
#define F_DIM   256
#define ALPHA_F 0.1f
#define EPS_F   1e-8f

#define BM      32
#define BN      128

// ---------------- device scratch ----------------
__device__ float g_ps[B_BATCH * 2];             // per-row partial sum [row][half]
__device__ float g_pp[B_BATCH * 2];             // per-row partial p_lbl
__device__ unsigned int g_done[B_BATCH / BM];   // per-row-group tickets (monotonic)

// ---------------- helpers ----------------
__device__ __forceinline__ uint32_t smem_u32(const void* p) {
    uint32_t a;
    asm("{ .reg .u64 t; cvta.to.shared.u64 t, %1; cvt.u32.u64 %0, t; }"
        : "=r"(a) : "l"(p));
    return a;
}
__device__ __forceinline__ void ldmatrix_x4(uint32_t* r, uint32_t addr) {
    asm volatile("ldmatrix.sync.aligned.m8n8.x4.shared.b16 {%0,%1,%2,%3}, [%4];"
                 : "=r"(r[0]), "=r"(r[1]), "=r"(r[2]), "=r"(r[3]) : "r"(addr));
}
__device__ __forceinline__ void mma16816(float* d, const uint32_t* a,
                                         uint32_t b0, uint32_t b1) {
    asm volatile(
        "mma.sync.aligned.m16n8k16.row.col.f32.bf16.bf16.f32 "
        "{%0,%1,%2,%3}, {%4,%5,%6,%7}, {%8,%9}, {%0,%1,%2,%3};"
        : "+f"(d[0]), "+f"(d[1]), "+f"(d[2]), "+f"(d[3])
        : "r"(a[0]), "r"(a[1]), "r"(a[2]), "r"(a[3]), "r"(b0), "r"(b1));
}
__device__ __forceinline__ uint32_t pack_pair(float x) {
    __nv_bfloat162 p = __floats2bfloat162_rn(x * x, x);           // (x^2, x)
    return *(uint32_t*)&p;
}
__device__ __forceinline__ uint32_t pack_iv(float iv, float m) {
    __nv_bfloat162 p = __floats2bfloat162_rn(iv, -2.0f * m * iv); // (iv, -2m*iv)
    return *(uint32_t*)&p;
}

// ---------------------------------------------------------------------------
// Smem (bytes): B 128x1024 | A 32x1024 | sK 512 | sInv 512 | sPS 1K | sPP 1K | flag
// ---------------------------------------------------------------------------
#define SM_B    0
#define SM_A    131072
#define SM_K    163840
#define SM_I    164352
#define SM_PS   164864
#define SM_PP   165888
#define SM_FLAG 166912
#define SMEM_TOTAL 167936

__global__ __launch_bounds__(256, 1) void lgm_kernel(
    const float* __restrict__ feat,
    const int* __restrict__ labels,
    const float* __restrict__ means,
    const float* __restrict__ vars_,
    float* __restrict__ out) {
    extern __shared__ char smem[];
    const int tid  = threadIdx.x;
    const int wid  = tid >> 5;
    const int lane = tid & 31;
    const int bid  = blockIdx.x;
    const int grp  = bid >> 1;            // row group (32 rows)
    const int hh   = bid & 1;             // class half
    const int bRow0 = grp * BM;
    const int cls0  = hh * BN;
    const uint32_t sbase = smem_u32(smem);

    float* sK   = (float*)(smem + SM_K);            // [128] local classes
    float* sInv = (float*)(smem + SM_I);
    float* sPS  = (float*)(smem + SM_PS);           // [32 rows][8 warps]
    float* sPP  = (float*)(smem + SM_PP);
    int*   sFlag = (int*)(smem + SM_FLAG);

    const float4* mv4 = (const float4*)means;       // 64 f4 per class
    const float4* vv4 = (const float4*)vars_;
    const float4* featv = (const float4*)feat;      // 64 f4 per row

    // ---- passthrough: 4KB means + 4KB vars per CTA (distributed) ----
    {
        int j = bid * 128 + (tid & 127);
        if (tid < 128) ((float4*)(out + B_BATCH))[j] = mv4[j];
        else ((float4*)(out + B_BATCH + C_CLS * F_DIM))[j] = vv4[j];
    }

    // ---- A: load 32 rows x 256 feats, convert to (x^2,x) pairs ----
    const int ar = tid >> 3, as = tid & 7;          // row, seg-base
    float4 aR[8];
    #pragma unroll
    for (int u = 0; u < 8; u++)
        aR[u] = featv[(size_t)(bRow0 + ar) * 64 + as + u * 8];

    // ---- B: thread owns (class c = tid>>1, half h = tid&1) = 128 feats ----
    const int c = tid >> 1, h = tid & 1;
    const int gc = cls0 + c;
    const float4* mb = mv4 + (size_t)gc * 64 + h * 32;
    const float4* vb = vv4 + (size_t)gc * 64 + h * 32;
    char* brow = smem + SM_B + c * 1024;
    const int cx = c & 7;
    float ks = 0.0f, prod = 1.0f;
    #pragma unroll 2
    for (int i = 0; i < 8; i++) {
        float4 m[4], v[4];
        #pragma unroll
        for (int j = 0; j < 4; j++) { m[j] = mb[i * 4 + j]; v[j] = vb[i * 4 + j]; }
        #pragma unroll
        for (int j = 0; j < 4; j++) {
            float i0 = __fdividef(1.0f, v[j].x + EPS_F);
            float i1 = __fdividef(1.0f, v[j].y + EPS_F);
            float i2 = __fdividef(1.0f, v[j].z + EPS_F);
            float i3 = __fdividef(1.0f, v[j].w + EPS_F);
            uint4 w;
            w.x = pack_iv(i0, m[j].x);
            w.y = pack_iv(i1, m[j].y);
            w.z = pack_iv(i2, m[j].z);
            w.w = pack_iv(i3, m[j].w);
            int seg = h * 32 + i * 4 + j;
            *(uint4*)(brow + ((seg ^ cx) << 4)) = w;
            ks += m[j].x * m[j].x * i0 + m[j].y * m[j].y * i1
                + m[j].z * m[j].z * i2 + m[j].w * m[j].w * i3;
            prod *= v[j].x * v[j].y * v[j].z * v[j].w;
        }
    }
    // combine halves (partner = lane^1), write K and 1/(det^2+eps)
    {
        float ks2 = ks + __shfl_xor_sync(0xffffffffu, ks, 1);
        float pr2 = prod * __shfl_xor_sync(0xffffffffu, prod, 1);
        if (h == 0) {
            sK[c] = ks2;
            sInv[c] = 1.0f / (pr2 * pr2 + EPS_F);
        }
    }
    // stage A (swizzled, same XOR scheme)
    #pragma unroll
    for (int u = 0; u < 8; u++) {
        float4 v = aR[u];
        uint4 w;
        w.x = pack_pair(v.x); w.y = pack_pair(v.y);
        w.z = pack_pair(v.z); w.w = pack_pair(v.w);
        int seg = as + u * 8;
        *(uint4*)(smem + SM_A + ar * 1024 + ((seg ^ (ar & 7)) << 4)) = w;
    }
    __syncthreads();

    // ---- mainloop: 32 x k16 steps, warp tile 32 rows x 16 local cols ----
    float acc[2][2][4] = {};
    #pragma unroll 8
    for (int kk = 0; kk < 32; kk++) {
        uint32_t a[2][4], b[4];
        #pragma unroll
        for (int mt = 0; mt < 2; mt++) {
            int row = mt * 16 + (lane & 15);
            int seg = kk * 2 + ((lane >> 4) & 1);
            ldmatrix_x4(a[mt], sbase + SM_A + (uint32_t)(row * 1024
                               + ((seg ^ (row & 7)) << 4)));
        }
        {
            int row = wid * 16 + (lane & 7) + ((lane >> 4) & 1) * 8;
            int seg = kk * 2 + ((lane >> 3) & 1);
            ldmatrix_x4(b, sbase + SM_B + (uint32_t)(row * 1024
                               + ((seg ^ (row & 7)) << 4)));
        }
        #pragma unroll
        for (int mt = 0; mt < 2; mt++) {
            mma16816(acc[mt][0], a[mt], b[0], b[1]);
            mma16816(acc[mt][1], a[mt], b[2], b[3]);
        }
    }

    // ---- epilogue: prob + partial row sums ----
    const int r0 = lane >> 2;
    int lbls[2][2];
    #pragma unroll
    for (int mt = 0; mt < 2; mt++) {
        lbls[mt][0] = labels[bRow0 + mt * 16 + r0];
        lbls[mt][1] = labels[bRow0 + mt * 16 + r0 + 8];
    }
    float sums[2][2] = {{0.f,0.f},{0.f,0.f}};
    float pls [2][2] = {{0.f,0.f},{0.f,0.f}};
    #pragma unroll
    for (int nt = 0; nt < 2; nt++) {
        int lc0 = wid * 16 + nt * 8 + (lane & 3) * 2;   // local class
        int c0 = cls0 + lc0, c1 = c0 + 1;
        float k0 = sK[lc0], k1 = sK[lc0 + 1];
        float i0 = sInv[lc0], i1 = sInv[lc0 + 1];
        #pragma unroll
        for (int mt = 0; mt < 2; mt++) {
            #pragma unroll
            for (int hx = 0; hx < 2; hx++) {
                int lbl = lbls[mt][hx];
                float d0 = 0.5f * (acc[mt][nt][hx * 2 + 0] + k0);
                float d1 = 0.5f * (acc[mt][nt][hx * 2 + 1] + k1);
                if (c0 == lbl) d0 *= (1.0f + ALPHA_F);
                if (c1 == lbl) d1 *= (1.0f + ALPHA_F);
                float p0 = __expf(-d0) * i0;
                float p1 = __expf(-d1) * i1;
                sums[mt][hx] += p0 + p1;
                if (c0 == lbl) pls[mt][hx] += p0;
                if (c1 == lbl) pls[mt][hx] += p1;
            }
        }
    }
    #pragma unroll
    for (int o = 1; o < 4; o <<= 1) {
        #pragma unroll
        for (int mt = 0; mt < 2; mt++) {
            #pragma unroll
            for (int hx = 0; hx < 2; hx++) {
                sums[mt][hx] += __shfl_xor_sync(0xffffffffu, sums[mt][hx], o);
                pls [mt][hx] += __shfl_xor_sync(0xffffffffu, pls [mt][hx], o);
            }
        }
    }
    if ((lane & 3) == 0) {
        #pragma unroll
        for (int mt = 0; mt < 2; mt++) {
            #pragma unroll
            for (int hx = 0; hx < 2; hx++) {
                int rloc = mt * 16 + r0 + hx * 8;
                sPS[rloc * 8 + wid] = sums[mt][hx];
                sPP[rloc * 8 + wid] = pls[mt][hx];
            }
        }
    }
    __syncthreads();

    // ---- cross-half combine via monotonic tickets (no cluster) ----
    if (tid < BM) {
        float s = 0.f, pl = 0.f;
        #pragma unroll
        for (int w = 0; w < 8; w++) {
            s  += sPS[tid * 8 + w];
            pl += sPP[tid * 8 + w];
        }
        g_ps[(bRow0 + tid) * 2 + hh] = s;
        g_pp[(bRow0 + tid) * 2 + hh] = pl;
        __threadfence();
    }
    __syncthreads();
    if (tid == 0) {
        unsigned tk = atomicAdd(&g_done[grp], 1u);
        *sFlag = (int)(tk & 1u);          // odd ticket = second arriver
    }
    __syncthreads();
    if (*sFlag && tid < BM) {
        __threadfence();
        int b = bRow0 + tid;
        float s  = g_ps[b * 2] + g_ps[b * 2 + 1];
        float pl = g_pp[b * 2] + g_pp[b * 2 + 1];
        out[b] = -logf(pl / (s + EPS_F) + EPS_F);
    }
}

// ---------------------------------------------------------------------------
extern "C" void kernel_launch(void* const* d_in, const int* in_sizes, int n_in,
                              void* d_out, int out_size) {
    const float* feat   = (const float*)d_in[0];
    const int*   labels = (const int*)d_in[1];
    const float* means  = (const float*)d_in[2];
    const float* vars_  = (const float*)d_in[3];
    float* out = (float*)d_out;

    cudaFuncSetAttribute(lgm_kernel,
                         cudaFuncAttributeMaxDynamicSharedMemorySize, SMEM_TOTAL);

    lgm_kernel<<<128, 256, SMEM_TOTAL>>>(feat, labels, means, vars_, out);
}

// round 12
// speedup vs baseline: 1.4742x; 1.4742x over previous
#include <cuda_runtime.h>
#include <cuda_bf16.h>
#include <cstdint>

// LGMLoss on GB300 — Round 12: single fused kernel = R6's proven GEMM config
// (BM=32, BN=256, grid 64, depth-2 bulk B pipeline) + in-kernel precompute
// behind a 64-CTA epoch barrier. Loss fully in-CTA (no tail).

#define B_BATCH 2048
#define C_CLS   256
#define F_DIM   256
#define ALPHA_F 0.1f
#define EPS_F   1e-8f

#define BM      32
#define NCHUNK  4              // K split: 4 chunks of 128 bf16 (64 features)
#define STR     272            // A smem row stride (256B + 16 pad)
#define B_CHUNK_BYTES 65536    // 256 rows x 256B

// ---------------- device scratch ----------------
// B' pre-swizzled, chunk-major: [4][256 rows][64 words]; word = bf16x2 (iv,-2m*iv)
__device__ uint32_t g_Bchunks[NCHUNK * C_CLS * 64];
__device__ float g_K[C_CLS];
__device__ float g_invden[C_CLS];
__device__ unsigned int g_bar;          // epoch barrier (monotonic, never reset)

// ---------------- helpers ----------------
__device__ __forceinline__ uint32_t smem_u32(const void* p) {
    uint32_t a;
    asm("{ .reg .u64 t; cvta.to.shared.u64 t, %1; cvt.u32.u64 %0, t; }"
        : "=r"(a) : "l"(p));
    return a;
}
__device__ __forceinline__ void ldmatrix_x4(uint32_t* r, uint32_t addr) {
    asm volatile("ldmatrix.sync.aligned.m8n8.x4.shared.b16 {%0,%1,%2,%3}, [%4];"
                 : "=r"(r[0]), "=r"(r[1]), "=r"(r[2]), "=r"(r[3]) : "r"(addr));
}
__device__ __forceinline__ void mma16816(float* d, const uint32_t* a,
                                         uint32_t b0, uint32_t b1) {
    asm volatile(
        "mma.sync.aligned.m16n8k16.row.col.f32.bf16.bf16.f32 "
        "{%0,%1,%2,%3}, {%4,%5,%6,%7}, {%8,%9}, {%0,%1,%2,%3};"
        : "+f"(d[0]), "+f"(d[1]), "+f"(d[2]), "+f"(d[3])
        : "r"(a[0]), "r"(a[1]), "r"(a[2]), "r"(a[3]), "r"(b0), "r"(b1));
}
__device__ __forceinline__ uint32_t pack_pair(float x) {
    __nv_bfloat162 p = __floats2bfloat162_rn(x * x, x);           // (x^2, x)
    return *(uint32_t*)&p;
}
__device__ __forceinline__ uint32_t pack_iv(float iv, float m) {
    __nv_bfloat162 p = __floats2bfloat162_rn(iv, -2.0f * m * iv); // (iv, -2m*iv)
    return *(uint32_t*)&p;
}
#define MBAR_INIT(a, n) \
    asm volatile("mbarrier.init.shared.b64 [%0], %1;" :: "r"(a), "r"(n) : "memory")
#define MBAR_EXPECT_TX(a, tx) \
    asm volatile("mbarrier.arrive.expect_tx.shared.b64 _, [%0], %1;" \
                 :: "r"(a), "r"(tx) : "memory")
#define MBAR_WAIT(a, ph) do { \
    asm volatile("{ .reg .pred P; WL%=: mbarrier.try_wait.parity.acquire.cta.shared::cta.b64 P, [%0], %1, 0x989680;" \
                 " @P bra WD%=; bra WL%=; WD%=: }" :: "r"(a), "r"(ph) : "memory"); \
} while (0)
__device__ __forceinline__ void bulk_copy(uint32_t dst, const void* src,
                                          uint32_t bytes, uint32_t mbar) {
    asm volatile(
        "cp.async.bulk.shared::cluster.global.mbarrier::complete_tx::bytes "
        "[%0], [%1], %2, [%3];"
        :: "r"(dst), "l"(src), "r"(bytes), "r"(mbar) : "memory");
}

// ---------------------------------------------------------------------------
// Smem layout (bytes):
//   0: sK(1K) | 1024: sInv(1K) | 2048: sPS(1K)+sPP(1K) (phase-1 scratch reuse)
//   4096: mbar[2] (pad 128) | 4224: A 4 x 8704 | 39040: B 2 x 65536
// total 170112 -> 1 CTA/SM, 64 CTAs co-resident (epoch barrier safe)
// ---------------------------------------------------------------------------
#define SM_KOFF 0
#define SM_IOFF 1024
#define SM_RED  2048
#define SM_MBAR 4096
#define SM_A    4224
#define A_BUFSZ 8704
#define SM_B    39040
#define SMEM_TOTAL 170112

__global__ __launch_bounds__(256, 1) void lgm_fused_kernel(
    const float* __restrict__ feat,
    const int* __restrict__ labels,
    const float* __restrict__ means,
    const float* __restrict__ vars_,
    float* __restrict__ out) {
    extern __shared__ char smem[];
    const int tid  = threadIdx.x;
    const int wid  = tid >> 5;
    const int lane = tid & 31;
    const int bid  = blockIdx.x;
    const int bRow0 = bid * BM;
    const uint32_t sbase = smem_u32(smem);

    float* sK   = (float*)(smem + SM_KOFF);
    float* sInv = (float*)(smem + SM_IOFF);
    float* sPS  = (float*)(smem + SM_RED);          // [32 rows][8 warps]
    float* sPP  = sPS + 256;

    if (tid == 0) {
        MBAR_INIT(sbase + SM_MBAR, 1);
        MBAR_INIT(sbase + SM_MBAR + 8, 1);
    }

    // ---- A prefetch: all 4 chunks (LDGs fly during phase 1) ----
    const float4* featv = (const float4*)feat;      // 64 float4 per row
    const int ar = tid >> 3, as = tid & 7;          // 32 rows x 8 thread-cols
    float4 aReg[8];
    #pragma unroll
    for (int ci = 0; ci < NCHUNK; ci++) {
        aReg[ci * 2 + 0] = featv[(size_t)(bRow0 + ar) * 64 + ci * 16 + as];
        aReg[ci * 2 + 1] = featv[(size_t)(bRow0 + ar) * 64 + ci * 16 + as + 8];
    }

    // ---------------- phase 1: per-class precompute (4 classes/CTA) --------
    {
        const float4* mv4 = (const float4*)means;   // 64 f4 per class
        const float4* vv4 = (const float4*)vars_;
        const int cl  = wid >> 1;                   // local class 0..3
        const int c   = bid * 4 + cl;
        const int f4  = (wid & 1) * 32 + lane;      // float4 index within class
        float4 m = mv4[c * 64 + f4];
        float4 v = vv4[c * 64 + f4];
        float i0 = 1.0f / (v.x + EPS_F);
        float i1 = 1.0f / (v.y + EPS_F);
        float i2 = 1.0f / (v.z + EPS_F);
        float i3 = 1.0f / (v.w + EPS_F);
        uint4 w;
        w.x = pack_iv(i0, m.x); w.y = pack_iv(i1, m.y);
        w.z = pack_iv(i2, m.z); w.w = pack_iv(i3, m.w);
        {   // swizzled chunk-major store (4 consecutive pairs = one 16B seg)
            int f  = f4 * 4;
            int ck = f >> 6;
            int seg = (f & 63) >> 2;
            int idx = ck * (C_CLS * 64) + c * 64 + (((seg ^ (c & 7)) << 2));
            *(uint4*)&g_Bchunks[idx] = w;
        }
        ((float4*)(out + B_BATCH))[c * 64 + f4] = m;             // passthrough
        ((float4*)(out + B_BATCH + C_CLS * F_DIM))[c * 64 + f4] = v;

        float ks = m.x * m.x * i0 + m.y * m.y * i1
                 + m.z * m.z * i2 + m.w * m.w * i3;
        float pr = v.x * v.y * v.z * v.w;
        #pragma unroll
        for (int o = 16; o > 0; o >>= 1) {
            ks += __shfl_xor_sync(0xffffffffu, ks, o);
            pr *= __shfl_xor_sync(0xffffffffu, pr, o);
        }
        if (lane == 0) { sPS[wid] = ks; sPS[8 + wid] = pr; }     // scratch reuse
        __syncthreads();
        if (tid < 4) {
            float K   = sPS[2 * tid] + sPS[2 * tid + 1];
            float det = sPS[8 + 2 * tid] * sPS[8 + 2 * tid + 1];
            g_K[bid * 4 + tid] = K;
            g_invden[bid * 4 + tid] = 1.0f / (det * det + EPS_F);
        }
    }
    // stage all 4 A chunks (no staging in mainloop)
    #pragma unroll
    for (int u = 0; u < 8; u++) {
        int ci = u >> 1, j = u & 1;
        float4 v = aReg[u];
        uint4 w;
        w.x = pack_pair(v.x); w.y = pack_pair(v.y);
        w.z = pack_pair(v.z); w.w = pack_pair(v.w);
        *(uint4*)(smem + SM_A + ci * A_BUFSZ + ar * STR + (as + j * 8) * 16) = w;
    }

    // ---------------- device-wide epoch barrier (64 CTAs) ----------------
    __syncthreads();
    if (tid == 0) {
        __threadfence();
        unsigned tk = atomicAdd(&g_bar, 1u);
        unsigned target = (tk & ~63u) + 64u;
        unsigned cur;
        do {
            asm volatile("ld.acquire.gpu.global.b32 %0, [%1];"
                         : "=r"(cur) : "l"(&g_bar));
        } while (cur < target);
        asm volatile("fence.proxy.async;" ::: "memory");
        #pragma unroll
        for (int ci = 0; ci < 2; ci++) {
            uint32_t mb = sbase + SM_MBAR + ci * 8;
            MBAR_EXPECT_TX(mb, B_CHUNK_BYTES);
            bulk_copy(sbase + SM_B + ci * B_CHUNK_BYTES,
                      g_Bchunks + ci * (C_CLS * 64), B_CHUNK_BYTES, mb);
        }
    }
    __syncthreads();
    sK[tid]   = g_K[tid];                 // valid after barrier
    sInv[tid] = g_invden[tid];

    // ---------------- mainloop (R6 structure) ----------------
    float acc[2][4][4] = {};
    int ph0 = 0, ph1 = 0;
    #pragma unroll
    for (int ci = 0; ci < NCHUNK; ci++) {
        const int buf = ci & 1;
        if (buf == 0) { MBAR_WAIT(sbase + SM_MBAR, ph0); ph0 ^= 1; }
        else          { MBAR_WAIT(sbase + SM_MBAR + 8, ph1); ph1 ^= 1; }

        const uint32_t sAu = sbase + SM_A + ci * A_BUFSZ;
        const uint32_t sBu = sbase + SM_B + buf * B_CHUNK_BYTES;
        #pragma unroll
        for (int ks = 0; ks < 8; ks++) {            // 8 x k16 per chunk
            uint32_t a[2][4], b[2][4];
            #pragma unroll
            for (int mt = 0; mt < 2; mt++) {
                ldmatrix_x4(a[mt], sAu + (uint32_t)(mt * 16 + (lane & 15)) * STR
                                  + (uint32_t)(ks * 32 + ((lane >> 4) & 1) * 16));
            }
            #pragma unroll
            for (int nt16 = 0; nt16 < 2; nt16++) {
                int brow = wid * 32 + nt16 * 16 + (lane & 7) + ((lane >> 4) & 1) * 8;
                int bseg = ks * 2 + ((lane >> 3) & 1);
                ldmatrix_x4(b[nt16], sBu + (uint32_t)(brow * 256
                                      + ((bseg ^ (brow & 7)) << 4)));
            }
            #pragma unroll
            for (int mt = 0; mt < 2; mt++) {
                #pragma unroll
                for (int nt = 0; nt < 4; nt++) {
                    mma16816(acc[mt][nt], a[mt],
                             b[nt >> 1][(nt & 1) * 2],
                             b[nt >> 1][(nt & 1) * 2 + 1]);
                }
            }
        }
        __syncthreads();       // all warps done with this B buffer
        if (ci + 2 < NCHUNK && tid == 0) {
            uint32_t mb = sbase + SM_MBAR + buf * 8;
            MBAR_EXPECT_TX(mb, B_CHUNK_BYTES);
            bulk_copy(sbase + SM_B + buf * B_CHUNK_BYTES,
                      g_Bchunks + (ci + 2) * (C_CLS * 64), B_CHUNK_BYTES, mb);
        }
    }

    // ---------------- epilogue: prob + fused loss (R6 verbatim) ----------
    const int r0 = lane >> 2;
    int lbls[2][2];
    #pragma unroll
    for (int mt = 0; mt < 2; mt++) {
        lbls[mt][0] = labels[bRow0 + mt * 16 + r0];
        lbls[mt][1] = labels[bRow0 + mt * 16 + r0 + 8];
    }
    float sums[2][2] = {{0.f,0.f},{0.f,0.f}};
    float pls [2][2] = {{0.f,0.f},{0.f,0.f}};
    #pragma unroll
    for (int nt = 0; nt < 4; nt++) {
        int c0 = wid * 32 + nt * 8 + (lane & 3) * 2;
        int c1 = c0 + 1;
        float k0 = sK[c0], k1 = sK[c1];
        float i0 = sInv[c0], i1 = sInv[c1];
        #pragma unroll
        for (int mt = 0; mt < 2; mt++) {
            #pragma unroll
            for (int h = 0; h < 2; h++) {
                int lbl = lbls[mt][h];
                float d0 = 0.5f * (acc[mt][nt][h * 2 + 0] + k0);
                float d1 = 0.5f * (acc[mt][nt][h * 2 + 1] + k1);
                if (c0 == lbl) d0 *= (1.0f + ALPHA_F);
                if (c1 == lbl) d1 *= (1.0f + ALPHA_F);
                float p0 = __expf(-d0) * i0;
                float p1 = __expf(-d1) * i1;
                sums[mt][h] += p0 + p1;
                if (c0 == lbl) pls[mt][h] += p0;
                if (c1 == lbl) pls[mt][h] += p1;
            }
        }
    }
    #pragma unroll
    for (int o = 1; o < 4; o <<= 1) {
        #pragma unroll
        for (int mt = 0; mt < 2; mt++) {
            #pragma unroll
            for (int h = 0; h < 2; h++) {
                sums[mt][h] += __shfl_xor_sync(0xffffffffu, sums[mt][h], o);
                pls [mt][h] += __shfl_xor_sync(0xffffffffu, pls [mt][h], o);
            }
        }
    }
    __syncthreads();                      // sPS scratch free for reduction
    if ((lane & 3) == 0) {
        #pragma unroll
        for (int mt = 0; mt < 2; mt++) {
            #pragma unroll
            for (int h = 0; h < 2; h++) {
                int rloc = mt * 16 + r0 + h * 8;
                sPS[rloc * 8 + wid] = sums[mt][h];
                sPP[rloc * 8 + wid] = pls[mt][h];
            }
        }
    }
    __syncthreads();
    if (tid < BM) {
        float s = 0.f, pl = 0.f;
        #pragma unroll
        for (int w = 0; w < 8; w++) {
            s  += sPS[tid * 8 + w];
            pl += sPP[tid * 8 + w];
        }
        out[bRow0 + tid] = -logf(pl / (s + EPS_F) + EPS_F);
    }
}

// ---------------------------------------------------------------------------
extern "C" void kernel_launch(void* const* d_in, const int* in_sizes, int n_in,
                              void* d_out, int out_size) {
    const float* feat   = (const float*)d_in[0];
    const int*   labels = (const int*)d_in[1];
    const float* means  = (const float*)d_in[2];
    const float* vars_  = (const float*)d_in[3];
    float* out = (float*)d_out;

    cudaFuncSetAttribute(lgm_fused_kernel,
                         cudaFuncAttributeMaxDynamicSharedMemorySize, SMEM_TOTAL);

    lgm_fused_kernel<<<C_CLS / 4, 256, SMEM_TOTAL>>>(
        feat, labels, means, vars_, out);
}

// round 14
// speedup vs baseline: 1.5000x; 1.0175x over previous
#include <cuda_runtime.h>
#include <cuda_bf16.h>
#include <cstdint>

// LGMLoss on GB300 — Round 13: 2 CTAs/SM. BM=16 x BN=128, grid 256,
// 84KB smem/CTA, fused single launch (256-CTA epoch barrier), depth-2
// bulk B pipeline, monotonic-ticket cross-half combine.

#define B_BATCH 2048
#define C_CLS   256
#define F_DIM   256
#define ALPHA_F 0.1f
#define EPS_F   1e-8f

#define BM      16
#define BN      128
#define NCHUNK  4              // K split: 4 chunks of 128 bf16 (64 features)
#define STR     272            // A smem row stride (256B + 16 pad)
#define B_CHUNK_BYTES 32768    // 128 rows x 256B

// ---------------- device scratch ----------------
// B' pre-swizzled, chunk-major: [4][256 rows][64 words]; word = bf16x2 (iv,-2m*iv)
__device__ uint32_t g_Bchunks[NCHUNK * C_CLS * 64];
__device__ float g_K[C_CLS];
__device__ float g_invden[C_CLS];
__device__ float g_ps[B_BATCH * 2];             // per-row partial sum [row][half]
__device__ float g_pp[B_BATCH * 2];             // per-row partial p_lbl
__device__ unsigned int g_done[B_BATCH / BM];   // per-row-group tickets (monotonic)
__device__ unsigned int g_bar;                  // epoch barrier (monotonic)

// ---------------- helpers ----------------
__device__ __forceinline__ uint32_t smem_u32(const void* p) {
    uint32_t a;
    asm("{ .reg .u64 t; cvta.to.shared.u64 t, %1; cvt.u32.u64 %0, t; }"
        : "=r"(a) : "l"(p));
    return a;
}
__device__ __forceinline__ void ldmatrix_x4(uint32_t* r, uint32_t addr) {
    asm volatile("ldmatrix.sync.aligned.m8n8.x4.shared.b16 {%0,%1,%2,%3}, [%4];"
                 : "=r"(r[0]), "=r"(r[1]), "=r"(r[2]), "=r"(r[3]) : "r"(addr));
}
__device__ __forceinline__ void mma16816(float* d, const uint32_t* a,
                                         uint32_t b0, uint32_t b1) {
    asm volatile(
        "mma.sync.aligned.m16n8k16.row.col.f32.bf16.bf16.f32 "
        "{%0,%1,%2,%3}, {%4,%5,%6,%7}, {%8,%9}, {%0,%1,%2,%3};"
        : "+f"(d[0]), "+f"(d[1]), "+f"(d[2]), "+f"(d[3])
        : "r"(a[0]), "r"(a[1]), "r"(a[2]), "r"(a[3]), "r"(b0), "r"(b1));
}
__device__ __forceinline__ uint32_t pack_pair(float x) {
    __nv_bfloat162 p = __floats2bfloat162_rn(x * x, x);           // (x^2, x)
    return *(uint32_t*)&p;
}
#define MBAR_INIT(a, n) \
    asm volatile("mbarrier.init.shared.b64 [%0], %1;" :: "r"(a), "r"(n) : "memory")
#define MBAR_EXPECT_TX(a, tx) \
    asm volatile("mbarrier.arrive.expect_tx.shared.b64 _, [%0], %1;" \
                 :: "r"(a), "r"(tx) : "memory")
#define MBAR_WAIT(a, ph) do { \
    asm volatile("{ .reg .pred P; WL%=: mbarrier.try_wait.parity.acquire.cta.shared::cta.b64 P, [%0], %1, 0x989680;" \
                 " @P bra WD%=; bra WL%=; WD%=: }" :: "r"(a), "r"(ph) : "memory"); \
} while (0)
__device__ __forceinline__ void bulk_copy(uint32_t dst, const void* src,
                                          uint32_t bytes, uint32_t mbar) {
    asm volatile(
        "cp.async.bulk.shared::cluster.global.mbarrier::complete_tx::bytes "
        "[%0], [%1], %2, [%3];"
        :: "r"(dst), "l"(src), "r"(bytes), "r"(mbar) : "memory");
}

// ---------------------------------------------------------------------------
// Smem (bytes): sK 512 | sInv 512 | sPS 512 | sPP 512 | flag+pad | mbar[2]
//   2304: A 4 x 4352 | 20480: B 2 x 32768   total 86016 -> 2 CTAs/SM
// ---------------------------------------------------------------------------
#define SM_K    0
#define SM_I    512
#define SM_PS   1024
#define SM_PP   1536
#define SM_FLAG 2048
#define SM_MBAR 2176
#define SM_A    2304
#define A_BUFSZ 4352
#define SM_B    20480
#define SMEM_TOTAL 86016

__global__ __launch_bounds__(256, 2) void lgm_fused_kernel(
    const float* __restrict__ feat,
    const int* __restrict__ labels,
    const float* __restrict__ means,
    const float* __restrict__ vars_,
    float* __restrict__ out) {
    extern __shared__ char smem[];
    const int tid  = threadIdx.x;
    const int wid  = tid >> 5;
    const int lane = tid & 31;
    const int bid  = blockIdx.x;
    const int grp  = bid >> 1;            // row group (16 rows)
    const int hh   = bid & 1;             // class half
    const int bRow0 = grp * BM;
    const uint32_t sbase = smem_u32(smem);

    float* sK   = (float*)(smem + SM_K);            // [128] local classes
    float* sInv = (float*)(smem + SM_I);
    float* sPS  = (float*)(smem + SM_PS);           // [16 rows][8 warps]
    float* sPP  = (float*)(smem + SM_PP);
    int*   sFlag = (int*)(smem + SM_FLAG);

    if (tid == 0) {
        MBAR_INIT(sbase + SM_MBAR, 1);
        MBAR_INIT(sbase + SM_MBAR + 8, 1);
    }

    // ---- A prefetch: all 4 chunks, 1 float4/thread/chunk (LDGs in flight) ----
    const float4* featv = (const float4*)feat;      // 64 float4 per row
    const int ar = tid >> 4, as = tid & 15;         // 16 rows x 16 segs
    float4 aReg[4];
    #pragma unroll
    for (int ci = 0; ci < NCHUNK; ci++)
        aReg[ci] = featv[(size_t)(bRow0 + ar) * 64 + ci * 16 + as];

    // ---------------- phase 1: per-class precompute (1 class/CTA) ----------
    {
        const int c = bid;                // class = bid (grid 256)
        const int t = tid;                // feature
        float v = vars_[c * F_DIM + t];
        float m = means[c * F_DIM + t];
        float iv = 1.0f / (v + EPS_F);
        __nv_bfloat162 pr2 = __floats2bfloat162_rn(iv, -2.0f * m * iv);
        {   // chunk-major, seg-swizzled store (R6-proven indexing)
            int ci = t >> 6, p = t & 63;
            int w = ci * (C_CLS * 64) + c * 64
                  + ((((p >> 2) ^ (c & 7)) << 2) | (p & 3));
            g_Bchunks[w] = *(uint32_t*)&pr2;
        }
        out[B_BATCH + c * F_DIM + t] = m;                        // passthrough
        out[B_BATCH + C_CLS * F_DIM + c * F_DIM + t] = v;

        float ks = m * m * iv;
        float pr = v;
        #pragma unroll
        for (int o = 16; o > 0; o >>= 1) {
            ks += __shfl_xor_sync(0xffffffffu, ks, o);
            pr *= __shfl_xor_sync(0xffffffffu, pr, o);
        }
        if (lane == 0) { sPS[wid] = ks; sPS[8 + wid] = pr; }     // scratch reuse
        __syncthreads();
        if (t == 0) {
            float K = 0.0f, det = 1.0f;
            #pragma unroll
            for (int i = 0; i < 8; i++) { K += sPS[i]; det *= sPS[8 + i]; }
            g_K[c] = K;
            g_invden[c] = 1.0f / (det * det + EPS_F);
        }
    }
    // stage all 4 A chunks
    #pragma unroll
    for (int ci = 0; ci < NCHUNK; ci++) {
        float4 v = aReg[ci];
        uint4 w;
        w.x = pack_pair(v.x); w.y = pack_pair(v.y);
        w.z = pack_pair(v.z); w.w = pack_pair(v.w);
        *(uint4*)(smem + SM_A + ci * A_BUFSZ + ar * STR + as * 16) = w;
    }

    // ---------------- device-wide epoch barrier (256 CTAs) ----------------
    const int start = bid & 3;            // rotated chunk order
    __syncthreads();
    if (tid == 0) {
        __threadfence();
        unsigned tk = atomicAdd(&g_bar, 1u);
        unsigned target = (tk & ~255u) + 256u;
        unsigned cur;
        do {
            asm volatile("ld.acquire.gpu.global.b32 %0, [%1];"
                         : "=r"(cur) : "l"(&g_bar));
        } while (cur < target);
        asm volatile("fence.proxy.async;" ::: "memory");
        #pragma unroll
        for (int i = 0; i < 2; i++) {
            int ci = (start + i) & 3;
            uint32_t mb = sbase + SM_MBAR + i * 8;
            MBAR_EXPECT_TX(mb, B_CHUNK_BYTES);
            bulk_copy(sbase + SM_B + i * B_CHUNK_BYTES,
                      g_Bchunks + ci * (C_CLS * 64) + hh * (BN * 64),
                      B_CHUNK_BYTES, mb);
        }
    }
    __syncthreads();
    if (tid < BN) sK[tid] = g_K[hh * BN + tid];               // valid now
    else          sInv[tid - BN] = g_invden[hh * BN + tid - BN];

    // ---------------- mainloop: warp = 16 rows x 16 local cols ----------
    float acc[2][4] = {};
    int ph0 = 0, ph1 = 0;
    #pragma unroll
    for (int i = 0; i < NCHUNK; i++) {
        const int ci = (start + i) & 3;
        const int buf = i & 1;
        if (buf == 0) { MBAR_WAIT(sbase + SM_MBAR, ph0); ph0 ^= 1; }
        else          { MBAR_WAIT(sbase + SM_MBAR + 8, ph1); ph1 ^= 1; }

        const uint32_t sAu = sbase + SM_A + ci * A_BUFSZ;
        const uint32_t sBu = sbase + SM_B + buf * B_CHUNK_BYTES;
        #pragma unroll
        for (int ks = 0; ks < 8; ks++) {
            uint32_t a[4], b[4];
            ldmatrix_x4(a, sAu + (uint32_t)(lane & 15) * STR
                           + (uint32_t)(ks * 32 + ((lane >> 4) & 1) * 16));
            {
                int brow = wid * 16 + (lane & 7) + ((lane >> 4) & 1) * 8;
                int bseg = ks * 2 + ((lane >> 3) & 1);
                ldmatrix_x4(b, sBu + (uint32_t)(brow * 256
                                  + ((bseg ^ (brow & 7)) << 4)));
            }
            mma16816(acc[0], a, b[0], b[1]);
            mma16816(acc[1], a, b[2], b[3]);
        }
        __syncthreads();       // buffer fully consumed by all warps
        if (i + 2 < NCHUNK && tid == 0) {
            int cin = (start + i + 2) & 3;
            uint32_t mb = sbase + SM_MBAR + buf * 8;
            MBAR_EXPECT_TX(mb, B_CHUNK_BYTES);
            bulk_copy(sbase + SM_B + buf * B_CHUNK_BYTES,
                      g_Bchunks + cin * (C_CLS * 64) + hh * (BN * 64),
                      B_CHUNK_BYTES, mb);
        }
    }

    // ---------------- epilogue: prob + partial row sums ----------------
    const int r0 = lane >> 2;
    const int lbl0 = labels[bRow0 + r0];
    const int lbl1 = labels[bRow0 + r0 + 8];
    float s0 = 0.f, s1 = 0.f, pl0 = 0.f, pl1 = 0.f;
    #pragma unroll
    for (int nt = 0; nt < 2; nt++) {
        int lc0 = wid * 16 + nt * 8 + (lane & 3) * 2;   // local class
        int c0 = hh * BN + lc0, c1 = c0 + 1;            // global class
        float k0 = sK[lc0], k1 = sK[lc0 + 1];
        float i0 = sInv[lc0], i1 = sInv[lc0 + 1];
        {
            float d0 = 0.5f * (acc[nt][0] + k0);
            float d1 = 0.5f * (acc[nt][1] + k1);
            if (c0 == lbl0) d0 *= (1.0f + ALPHA_F);
            if (c1 == lbl0) d1 *= (1.0f + ALPHA_F);
            float p0 = __expf(-d0) * i0;
            float p1 = __expf(-d1) * i1;
            s0 += p0 + p1;
            if (c0 == lbl0) pl0 += p0;
            if (c1 == lbl0) pl0 += p1;
        }
        {
            float d0 = 0.5f * (acc[nt][2] + k0);
            float d1 = 0.5f * (acc[nt][3] + k1);
            if (c0 == lbl1) d0 *= (1.0f + ALPHA_F);
            if (c1 == lbl1) d1 *= (1.0f + ALPHA_F);
            float p0 = __expf(-d0) * i0;
            float p1 = __expf(-d1) * i1;
            s1 += p0 + p1;
            if (c0 == lbl1) pl1 += p0;
            if (c1 == lbl1) pl1 += p1;
        }
    }
    #pragma unroll
    for (int o = 1; o < 4; o <<= 1) {
        s0  += __shfl_xor_sync(0xffffffffu, s0, o);
        s1  += __shfl_xor_sync(0xffffffffu, s1, o);
        pl0 += __shfl_xor_sync(0xffffffffu, pl0, o);
        pl1 += __shfl_xor_sync(0xffffffffu, pl1, o);
    }
    __syncthreads();                      // sPS scratch free
    if ((lane & 3) == 0) {
        sPS[r0 * 8 + wid]       = s0;
        sPS[(r0 + 8) * 8 + wid] = s1;
        sPP[r0 * 8 + wid]       = pl0;
        sPP[(r0 + 8) * 8 + wid] = pl1;
    }
    __syncthreads();

    // ---------------- cross-half combine (monotonic tickets) ----------------
    if (tid < BM) {
        float s = 0.f, pl = 0.f;
        #pragma unroll
        for (int w = 0; w < 8; w++) {
            s  += sPS[tid * 8 + w];
            pl += sPP[tid * 8 + w];
        }
        g_ps[(bRow0 + tid) * 2 + hh] = s;
        g_pp[(bRow0 + tid) * 2 + hh] = pl;
        __threadfence();
    }
    __syncthreads();
    if (tid == 0) {
        unsigned tk = atomicAdd(&g_done[grp], 1u);
        *sFlag = (int)(tk & 1u);          // odd ticket = second arriver
    }
    __syncthreads();
    if (*sFlag && tid < BM) {
        __threadfence();
        int b = bRow0 + tid;
        float s  = g_ps[b * 2] + g_ps[b * 2 + 1];
        float pl = g_pp[b * 2] + g_pp[b * 2 + 1];
        out[b] = -logf(pl / (s + EPS_F) + EPS_F);
    }
}

// ---------------------------------------------------------------------------
extern "C" void kernel_launch(void* const* d_in, const int* in_sizes, int n_in,
                              void* d_out, int out_size) {
    const float* feat   = (const float*)d_in[0];
    const int*   labels = (const int*)d_in[1];
    const float* means  = (const float*)d_in[2];
    const float* vars_  = (const float*)d_in[3];
    float* out = (float*)d_out;

    cudaFuncSetAttribute(lgm_fused_kernel,
                         cudaFuncAttributeMaxDynamicSharedMemorySize, SMEM_TOTAL);

    lgm_fused_kernel<<<256, 256, SMEM_TOTAL>>>(feat, labels, means, vars_, out);
}